// round 12
// baseline (speedup 1.0000x reference)
#include <cuda_runtime.h>
#include <cstdint>

#define NIN      2049
#define NOUT     1024
#define THREADS  1024

// Caps sized generously above the actual shapes (n_tri*max_w = 9120).
#define WT_CAP   32768
#define JT_CAP   1024

__device__ float g_wT[WT_CAP];   // transposed tri weights: wT[w * n_tri + j]
__device__ int   g_i0[JT_CAP];   // tri window starts

// ---- Prep: transpose weights to w-major, extract window starts ----------
__global__ void prep_kernel(const float* __restrict__ triw,
                            const int*   __restrict__ tridx,
                            int n_tri, int max_w)
{
    const int tot    = n_tri * max_w;
    const int stride = gridDim.x * blockDim.x;
    for (int i = blockIdx.x * blockDim.x + threadIdx.x; i < tot; i += stride) {
        const int j = i / max_w;
        const int w = i - j * max_w;
        if (w * n_tri + j < WT_CAP)
            g_wT[w * n_tri + j] = triw[i];          // coalesced read
    }
    for (int j = blockIdx.x * blockDim.x + threadIdx.x; j < n_tri && j < JT_CAP;
         j += stride)
        g_i0[j] = tridx[(size_t)j * max_w];         // first entry always valid
}

// ---- Main: one frame per CTA, one output column per thread --------------
__global__ void __launch_bounds__(THREADS, 2)
logscale_kernel(const float* __restrict__ x,
                const float* __restrict__ frac,
                const float* __restrict__ cubt,
                const int*   __restrict__ pair,
                const int*   __restrict__ cubi,
                float* __restrict__ out,
                int n_lin, int n_cub, int n_tri, int max_w)
{
    __shared__ float sx[NIN];

    const int row = blockIdx.x;
    const int t   = threadIdx.x;
    const float* __restrict__ xr = x + (size_t)row * NIN;

    // Stage the row: 2049 floats, two coalesced passes + tail (rows are only
    // 4B-aligned, so scalar loads; latency hidden by 64 warps/SM).
    sx[t]           = __ldg(xr + t);
    sx[t + THREADS] = __ldg(xr + t + THREADS);
    if (t == 0) sx[2048] = __ldg(xr + 2048);
    __syncthreads();

    const int n_sum = n_lin + n_cub;
    float v;

    if (t < n_lin) {
        // Linear: x0 + f*(x1-x0)
        const int   i0 = __ldg(pair + t);
        const float f  = __ldg(frac + t);
        const float x0 = sx[i0];
        v = x0 + f * (sx[i0 + 1] - x0);
    } else if (t < n_sum) {
        // Catmull-Rom cubic
        const int   j  = t - n_lin;
        const int   i0 = __ldg(cubi + j);
        const float tc = __ldg(cubt + j);
        const float xm1 = sx[i0 - 1];
        const float x0  = sx[i0];
        const float x1  = sx[i0 + 1];
        const float x2  = sx[i0 + 2];
        v = x0 + 0.5f * tc * (x1 - xm1
          + tc * (2.0f * xm1 - 5.0f * x0 + 4.0f * x1 - x2
          + tc * (3.0f * (x0 - x1) + x2 - xm1)));
    } else {
        // Triangular: max over window of sx[i0+w] + weight. Weights read
        // w-major (lanes = consecutive j -> coalesced). Padded slots are
        // exactly -inf (valid weights bottom at -160 dB) -> per-lane break;
        // adjacent window lengths are similar, so warp trip ~ window length.
        const int j  = t - n_sum;
        const int i0 = g_i0[j];
        const float* __restrict__ wT = g_wT + j;
        float m = __int_as_float(0xff800000);

        bool done = false;
        for (int wb = 0; wb < max_w && !done; wb += 4) {
            float wv[4];
            #pragma unroll
            for (int c = 0; c < 4; c++)
                wv[c] = (wb + c < max_w) ? __ldg(wT + (wb + c) * n_tri)
                                         : __int_as_float(0xff800000);
            #pragma unroll
            for (int c = 0; c < 4; c++) {
                if (__float_as_int(wv[c]) == (int)0xff800000) { done = true; break; }
                m = fmaxf(m, sx[i0 + wb + c] + wv[c]);
            }
        }
        v = m;
    }

    out[(size_t)row * NOUT + t] = v;    // fully coalesced
}

extern "C" void kernel_launch(void* const* d_in, const int* in_sizes, int n_in,
                              void* d_out, int out_size)
{
    const float* x     = (const float*)d_in[0];
    const float* frac  = (const float*)d_in[1];
    const float* cubt  = (const float*)d_in[2];
    const float* triw  = (const float*)d_in[3];
    const int*   pair  = (const int*)d_in[4];
    const int*   cubi  = (const int*)d_in[5];
    const int*   tridx = (const int*)d_in[6];
    float* out = (float*)d_out;

    const int n_lin  = in_sizes[1];
    const int n_cub  = in_sizes[2];
    const int n_tri  = NOUT - n_lin - n_cub;
    const int max_w  = (n_tri > 0) ? in_sizes[3] / n_tri : 0;
    const int n_rows = in_sizes[0] / NIN;

    if (n_tri > 0)
        prep_kernel<<<36, 256>>>(triw, tridx, n_tri, max_w);

    logscale_kernel<<<n_rows, THREADS>>>(x, frac, cubt, pair, cubi, out,
                                         n_lin, n_cub, n_tri, max_w);
}

// round 13
// speedup vs baseline: 1.4971x; 1.4971x over previous
#include <cuda_runtime.h>
#include <cstdint>

#define NIN      2049   // inputs per frame
#define NOUT     1024   // outputs per frame
#define ROWS     6      // frames per CTA -> grid = 267, 2 CTAs/SM, single wave
#define THREADS  1024

__global__ void __launch_bounds__(THREADS, 2)
logscale_kernel(const float* __restrict__ x,
                const float* __restrict__ frac,
                const float* __restrict__ cubt,
                const float* __restrict__ triw,
                const int*   __restrict__ pair,
                const int*   __restrict__ cubi,
                const int*   __restrict__ tridx,
                float* __restrict__ out,
                int n_rows, int n_lin, int n_cub, int max_w, int n_tri)
{
    // Shared: sx[ROWS*NIN] | swt[n_tri*(max_w+1)] | si0[n_tri] | slen[n_tri]
    extern __shared__ float smem_pool[];
    const int wstride = max_w + 1;             // 41 -> stride 9 mod 32
    float* sx   = smem_pool;
    float* swt  = smem_pool + ROWS * NIN;
    int*   si0  = (int*)(swt + n_tri * wstride);
    int*   slen = si0 + n_tri;

    const int row0  = blockIdx.x * ROWS;
    const int nr    = min(ROWS, n_rows - row0);
    const int t     = threadIdx.x;
    const int n_sum = n_lin + n_cub;
    const float NEG_INF = __int_as_float(0xff800000);

    // ---- init per-j window-length table ----
    if (t < n_tri) slen[t] = max_w;
    __syncthreads();

    // ---- Staging: x tile (float2, front-batched), weights(+len), i0 ----
    {
        // 6*2049 floats = odd multiple of 8B -> float2 always aligned.
        const float2* s2 = (const float2*)(x + (size_t)row0 * NIN);
        float2* d2       = (float2*)sx;
        const int nv     = (nr * NIN) >> 1;    // nr*NIN even (nr in {6,4})
        #pragma unroll
        for (int u = 0; u < 6; u++) {
            const int i = t + u * THREADS;
            if (i < nv) d2[i] = s2[i];
        }
        { const int i = t + 6 * THREADS; if (i < nv) d2[i] = s2[i]; }

        // weights: coalesced read, padded write; record first -inf per j.
        const int wtot = n_tri * max_w;
        for (int i = t; i < wtot; i += THREADS) {
            const int j = i / max_w;
            const int w = i - j * max_w;
            const float v = __ldg(triw + i);
            swt[j * wstride + w] = v;
            if (__float_as_int(v) == (int)0xff800000) atomicMin(&slen[j], w);
        }
        if (t < n_tri)
            si0[t] = __ldg(tridx + (size_t)t * max_w);  // first entry always valid
    }
    __syncthreads();

    // ---- Triangular: task = (j, 3-row half); j DESCENDING in thread id ---
    // 2*n_tri = 456 tasks on threads 0..455; longest windows go to threads
    // with no Phase-A work. 3 independent max chains; exact trip count.
    if (t < 2 * n_tri) {
        const int j   = n_tri - 1 - (t >> 1);
        const int q3  = (t & 1) * 3;           // rows q3..q3+2
        const int i0  = si0[j];
        const int len = slen[j];
        const float* __restrict__ wp = swt + j * wstride;
        const float* __restrict__ p  = sx + q3 * NIN + i0;

        float m0 = NEG_INF, m1 = NEG_INF, m2 = NEG_INF;
        #pragma unroll 4
        for (int w = 0; w < len; w++) {
            const float wg = wp[w];
            m0 = fmaxf(m0, p[w]           + wg);
            m1 = fmaxf(m1, p[NIN + w]     + wg);
            m2 = fmaxf(m2, p[2 * NIN + w] + wg);
        }
        const int o = n_sum + j;
        if (q3 + 0 < nr) out[(size_t)(row0 + q3 + 0) * NOUT + o] = m0;
        if (q3 + 1 < nr) out[(size_t)(row0 + q3 + 1) * NOUT + o] = m1;
        if (q3 + 2 < nr) out[(size_t)(row0 + q3 + 2) * NOUT + o] = m2;
    }

    // ---- Linear + cubic on the high threads (o = t - (1024 - n_sum)) -----
    {
        const int o = t - (THREADS - n_sum);
        if (o >= 0) {
            if (o < n_lin) {
                const int   i0 = __ldg(pair + o);
                const float f  = __ldg(frac + o);
                #pragma unroll
                for (int r = 0; r < ROWS; r++) {
                    const float x0 = sx[r * NIN + i0];
                    const float x1 = sx[r * NIN + i0 + 1];
                    if (r < nr)
                        out[(size_t)(row0 + r) * NOUT + o] = x0 + f * (x1 - x0);
                }
            } else {
                const int   j  = o - n_lin;
                const int   i0 = __ldg(cubi + j);
                const float tc = __ldg(cubt + j);
                #pragma unroll
                for (int r = 0; r < ROWS; r++) {
                    const float* row = sx + r * NIN;
                    const float xm1 = row[i0 - 1];
                    const float x0  = row[i0];
                    const float x1  = row[i0 + 1];
                    const float x2  = row[i0 + 2];
                    const float v = x0 + 0.5f * tc * (x1 - xm1
                                  + tc * (2.0f * xm1 - 5.0f * x0 + 4.0f * x1 - x2
                                  + tc * (3.0f * (x0 - x1) + x2 - xm1)));
                    if (r < nr)
                        out[(size_t)(row0 + r) * NOUT + o] = v;
                }
            }
        }
    }
}

extern "C" void kernel_launch(void* const* d_in, const int* in_sizes, int n_in,
                              void* d_out, int out_size)
{
    const float* x     = (const float*)d_in[0];
    const float* frac  = (const float*)d_in[1];
    const float* cubt  = (const float*)d_in[2];
    const float* triw  = (const float*)d_in[3];
    const int*   pair  = (const int*)d_in[4];
    const int*   cubi  = (const int*)d_in[5];
    const int*   tridx = (const int*)d_in[6];
    float* out = (float*)d_out;

    const int n_lin  = in_sizes[1];
    const int n_cub  = in_sizes[2];
    const int n_tri  = NOUT - n_lin - n_cub;
    const int max_w  = (n_tri > 0) ? in_sizes[3] / n_tri : 0;
    const int n_rows = in_sizes[0] / NIN;

    // smem: x tile + padded weights + i0 + len  (~86.4 KB -> 2 CTAs/SM)
    const int smem = (ROWS * NIN + n_tri * (max_w + 1) + 2 * n_tri)
                     * (int)sizeof(float);
    cudaFuncSetAttribute(logscale_kernel,
                         cudaFuncAttributeMaxDynamicSharedMemorySize, smem);

    const int grid = (n_rows + ROWS - 1) / ROWS;   // 267 CTAs for 1600 rows
    logscale_kernel<<<grid, THREADS, smem>>>(x, frac, cubt, triw,
                                             pair, cubi, tridx, out,
                                             n_rows, n_lin, n_cub, max_w, n_tri);
}